// round 5
// baseline (speedup 1.0000x reference)
#include <cuda_runtime.h>
#include <math.h>
#include <stdint.h>

#define BB 32
#define SS 4096
#define II 512
#define HH 512
#define NCH 32
#define CHUNK (SS / NCH)      // 128 positions per block
#define TILE 16               // positions per shared tile
#define NTILES (CHUNK / TILE) // 8
#define NTHREADS 256
#define NEG_INF_F (-1e18f)
#define HSPLIT 8

// -------- persistent device scratch (no allocations allowed) --------
__device__ float g_part[2 * HSPLIT * II];  // [mat][hs][i] partials (0=Wk->w2, 1=Wq->wq2)
__device__ float g_w2[II];                 // Wk^T @ Wout
__device__ float g_qoff[BB];               // per-batch additive score offset
__device__ float g_pm[BB * NCH];           // partial max
__device__ float g_pl[BB * NCH];           // partial sumexp
__device__ float g_pkbar[BB * NCH * II];   // partial weighted key sums

// -------- cp.async helpers --------
__device__ __forceinline__ void cp_async16(void* dst_smem, const void* src_gmem) {
    unsigned d = (unsigned)__cvta_generic_to_shared(dst_smem);
    asm volatile("cp.async.cg.shared.global [%0], [%1], 16;\n" :: "r"(d), "l"(src_gmem));
}
__device__ __forceinline__ void cp_async_commit() {
    asm volatile("cp.async.commit_group;\n");
}
__device__ __forceinline__ void cp_async_wait1() {
    asm volatile("cp.async.wait_group 1;\n");
}
__device__ __forceinline__ void cp_async_wait0() {
    asm volatile("cp.async.wait_group 0;\n");
}

// ============================================================
// Kernel A1: partial projected-weight vectors.
// 256 blocks: mat(2) x hsplit(8) x igroup(16). 256 threads:
// il(32) x hsub(8). Coalesced 128B loads.
// ============================================================
__global__ void __launch_bounds__(256) prep_partial(
    const float* __restrict__ Wk, const float* __restrict__ Wq,
    const float* __restrict__ Wout)
{
    const int blk = blockIdx.x;
    const int mat = blk >> 7;          // 0: Wk, 1: Wq
    const int rem = blk & 127;
    const int hs  = rem >> 4;          // 0..7
    const int ig  = rem & 15;          // 0..15
    const int i0  = ig * 32;
    const int h0  = hs * 64;
    const int tid = threadIdx.x;
    const int il   = tid & 31;
    const int hsub = tid >> 5;         // 0..7

    const float* W = mat ? Wq : Wk;

    __shared__ float wout_sh[64];
    __shared__ float red[256];
    if (tid < 64) wout_sh[tid] = Wout[h0 + tid];
    __syncthreads();

    float acc = 0.f;
    #pragma unroll
    for (int k = 0; k < 8; k++) {
        int hl = hsub * 8 + k;
        acc += W[(size_t)(h0 + hl) * II + i0 + il] * wout_sh[hl];
    }
    red[tid] = acc;
    __syncthreads();
    if (tid < 128) red[tid] += red[tid + 128];
    __syncthreads();
    if (tid < 64) red[tid] += red[tid + 64];
    __syncthreads();
    if (tid < 32) {
        float v = red[tid] + red[tid + 32];
        g_part[(mat * HSPLIT + hs) * II + i0 + tid] = v;
    }
}

// ============================================================
// Kernel A2: combine partials. Blocks 0..31: qoff[b].
// Block 32: g_w2.
// ============================================================
__global__ void __launch_bounds__(512) prep_combine(
    const float* __restrict__ query,
    const float* __restrict__ bq, const float* __restrict__ bk,
    const float* __restrict__ Wout)
{
    const int tid = threadIdx.x;
    if (blockIdx.x == 32) {
        float s = 0.f;
        #pragma unroll
        for (int hs = 0; hs < HSPLIT; hs++)
            s += g_part[hs * II + tid];
        g_w2[tid] = s;
        return;
    }
    const int b = blockIdx.x;
    __shared__ float wq2_sh[II];
    __shared__ float red[512];

    float s = 0.f;
    #pragma unroll
    for (int hs = 0; hs < HSPLIT; hs++)
        s += g_part[(HSPLIT + hs) * II + tid];
    wq2_sh[tid] = s;

    // cbias = Wout . (bq + bk)
    red[tid] = Wout[tid] * (bq[tid] + bk[tid]);
    __syncthreads();
    for (int off = 256; off > 0; off >>= 1) {
        if (tid < off) red[tid] += red[tid + off];
        __syncthreads();
    }
    float cbias = red[0];
    __syncthreads();

    // qoff[b] = query[b,:] . wq2 + cbias
    red[tid] = query[(size_t)b * II + tid] * wq2_sh[tid];
    __syncthreads();
    for (int off = 256; off > 0; off >>= 1) {
        if (tid < off) red[tid] += red[tid + off];
        __syncthreads();
    }
    if (tid == 0) g_qoff[b] = red[0] + cbias;
}

// ============================================================
// Kernel B: single streaming pass over key. Per block: one
// (batch, S-chunk). Computes scores -> attn_weight (gmem), and
// online-softmax partials (m, l, kbar) -> scratch.
// ============================================================
__global__ void __launch_bounds__(NTHREADS) main_pass(
    const float* __restrict__ key,
    const int* __restrict__ mask,
    float* __restrict__ out)
{
    const int b = blockIdx.x / NCH;
    const int c = blockIdx.x % NCH;
    const int tid = threadIdx.x;
    const int lane = tid & 31;
    const int warp = tid >> 5;
    const int s0 = c * CHUNK;
    const float* keyb = key + (size_t)b * SS * II + (size_t)s0 * II;

    extern __shared__ float smem[];
    float* buf0  = smem;                 // TILE*II floats
    float* buf1  = smem + TILE * II;     // TILE*II floats
    float* sc_sh = smem + 2 * TILE * II; // TILE scores
    float* p_sh  = sc_sh + TILE;         // TILE probs + [TILE] = scale slot

    // w2 slice for this lane (fixed across all positions)
    float w2r[16];
    #pragma unroll
    for (int k = 0; k < 16; k++) w2r[k] = g_w2[lane + 32 * k];

    const float qoff = g_qoff[b];

    float kbar0 = 0.f, kbar1 = 0.f;  // thread owns i = tid, tid+256
    float l = 0.f;
    float m_run = -3.0e38f;

    // issue tile 0
    {
        const float* src = keyb;
        #pragma unroll
        for (int j = 0; j < 8; j++) {
            int idx = tid + j * NTHREADS; // float4 index, 2048 total
            cp_async16(buf0 + idx * 4, src + idx * 4);
        }
        cp_async_commit();
    }

    for (int t = 0; t < NTILES; t++) {
        float* cur = (t & 1) ? buf1 : buf0;
        if (t + 1 < NTILES) {
            float* nxt = (t & 1) ? buf0 : buf1;
            const float* src = keyb + (size_t)(t + 1) * TILE * II;
            #pragma unroll
            for (int j = 0; j < 8; j++) {
                int idx = tid + j * NTHREADS;
                cp_async16(nxt + idx * 4, src + idx * 4);
            }
            cp_async_commit();
            cp_async_wait1();
        } else {
            cp_async_wait0();
        }
        __syncthreads();

        // ---- scores: each warp does 2 positions ----
        for (int tt = warp; tt < TILE; tt += 8) {
            const float* kr = cur + tt * II;
            float acc = 0.f;
            #pragma unroll
            for (int k = 0; k < 16; k++)
                acc += kr[lane + 32 * k] * w2r[k];
            #pragma unroll
            for (int off = 16; off > 0; off >>= 1)
                acc += __shfl_down_sync(0xffffffffu, acc, off);
            if (lane == 0) {
                int s = s0 + t * TILE + tt;
                float sc = acc + qoff;
                if (mask[(size_t)b * SS + s] != 0) sc = NEG_INF_F;
                sc_sh[tt] = sc;
            }
        }
        __syncthreads();

        // coalesced attn_weight store: one 64B transaction
        if (tid < TILE)
            out[(size_t)BB * HH + (size_t)b * SS + s0 + t * TILE + tid] = sc_sh[tid];

        // ---- online softmax update ----
        // m_new computed redundantly (cheap ALU); exps only in warp 0.
        float mt = -3.0e38f;
        #pragma unroll
        for (int tt = 0; tt < TILE; tt++) mt = fmaxf(mt, sc_sh[tt]);
        float m_new = fmaxf(m_run, mt);

        if (tid < TILE) p_sh[tid] = __expf(sc_sh[tid] - m_new);
        if (tid == 31) p_sh[TILE] = __expf(m_run - m_new);  // scale (m_run identical across threads)
        __syncthreads();

        float scale = p_sh[TILE];
        kbar0 *= scale;
        kbar1 *= scale;
        float tsum = 0.f;
        #pragma unroll
        for (int tt = 0; tt < TILE; tt++) {
            float p = p_sh[tt];
            tsum += p;
            kbar0 += p * cur[tt * II + tid];
            kbar1 += p * cur[tt * II + tid + 256];
        }
        l = l * scale + tsum;
        m_run = m_new;
        __syncthreads(); // buffer reuse fence
    }

    const int pidx = blockIdx.x;
    g_pkbar[(size_t)pidx * II + tid] = kbar0;
    g_pkbar[(size_t)pidx * II + tid + 256] = kbar1;
    if (tid == 0) { g_pm[pidx] = m_run; g_pl[pidx] = l; }
}

// ============================================================
// Kernel C: combine chunk partials (weights computed ONCE in
// warp 0), then attn[b, h0:h0+64] = kbar @ Wk^T + bk.
// grid = BB * 8 blocks, 256 threads.
// ============================================================
__global__ void __launch_bounds__(256) finalize(
    const float* __restrict__ Wk, const float* __restrict__ bk,
    float* __restrict__ out)
{
    const int b   = blockIdx.x >> 3;
    const int h0  = (blockIdx.x & 7) * 64;
    const int tid = threadIdx.x;
    const int lane = tid & 31;
    const int warp = tid >> 5;

    __shared__ float kbar_sh[II];
    __shared__ float w_sh[NCH];
    __shared__ float invl_sh;

    // warp 0: chunk weights + 1/l, exactly one exp per chunk
    if (warp == 0) {
        float pm = g_pm[b * NCH + lane];
        float pl = g_pl[b * NCH + lane];
        float M = pm;
        #pragma unroll
        for (int off = 16; off > 0; off >>= 1)
            M = fmaxf(M, __shfl_xor_sync(0xffffffffu, M, off));
        float w = __expf(pm - M);
        w_sh[lane] = w;
        float lw = pl * w;
        #pragma unroll
        for (int off = 16; off > 0; off >>= 1)
            lw += __shfl_xor_sync(0xffffffffu, lw, off);
        if (lane == 0) invl_sh = 1.f / lw;
    }
    __syncthreads();

    // combine chunk partials: pure FMA with shared-broadcast weights
    float kb0 = 0.f, kb1 = 0.f;
    #pragma unroll
    for (int c = 0; c < NCH; c++) {
        float w = w_sh[c];
        kb0 += g_pkbar[(size_t)(b * NCH + c) * II + tid] * w;
        kb1 += g_pkbar[(size_t)(b * NCH + c) * II + tid + 256] * w;
    }
    float invl = invl_sh;
    kbar_sh[tid] = kb0 * invl;
    kbar_sh[tid + 256] = kb1 * invl;
    __syncthreads();

    // each warp: 8 h-dots, lane-parallel float4 over i
    const float4* k4 = (const float4*)kbar_sh;
    #pragma unroll
    for (int j = 0; j < 8; j++) {
        int h = h0 + warp * 8 + j;
        const float4* w4 = (const float4*)(Wk + (size_t)h * II);
        float acc = 0.f;
        #pragma unroll
        for (int i = 0; i < 4; i++) {
            float4 a = w4[lane + i * 32];
            float4 c4 = k4[lane + i * 32];
            acc += a.x * c4.x + a.y * c4.y + a.z * c4.z + a.w * c4.w;
        }
        #pragma unroll
        for (int off = 16; off > 0; off >>= 1)
            acc += __shfl_down_sync(0xffffffffu, acc, off);
        if (lane == 0) out[b * HH + h] = acc + bk[h];
    }
}

// ============================================================
extern "C" void kernel_launch(void* const* d_in, const int* in_sizes, int n_in,
                              void* d_out, int out_size) {
    const float* query = (const float*)d_in[0];
    const float* key   = (const float*)d_in[1];
    const int*   mask  = (const int*)d_in[2];
    const float* Wq   = (const float*)d_in[3];
    const float* bq   = (const float*)d_in[4];
    const float* Wk   = (const float*)d_in[5];
    const float* bk   = (const float*)d_in[6];
    const float* Wout = (const float*)d_in[7];
    float* out = (float*)d_out;

    const size_t smem = (2 * TILE * II + 2 * TILE + 8) * sizeof(float);
    cudaFuncSetAttribute(main_pass, cudaFuncAttributeMaxDynamicSharedMemorySize, (int)smem);

    prep_partial<<<256, 256>>>(Wk, Wq, Wout);
    prep_combine<<<33, 512>>>(query, bq, bk, Wout);
    main_pass<<<BB * NCH, NTHREADS, smem>>>(key, mask, out);
    finalize<<<BB * 8, 256>>>(Wk, bk, out);
}

// round 6
// speedup vs baseline: 1.3469x; 1.3469x over previous
#include <cuda_runtime.h>
#include <math.h>
#include <stdint.h>

#define BB 32
#define SS 4096
#define II 512
#define HH 512
#define NCH 32
#define CHUNK (SS / NCH)      // 128 positions per block
#define TILE 8                // positions per shared tile
#define NTILES (CHUNK / TILE) // 16
#define NTHREADS 256
#define NEG_INF_F (-1e18f)
#define HSPLIT 8

// -------- persistent device scratch (no allocations allowed) --------
__device__ float g_part[2 * HSPLIT * II];  // [mat][hs][i] partials
__device__ float g_w2[II];                 // Wk^T @ Wout
__device__ float g_qoff[BB];               // per-batch additive score offset
__device__ float g_pm[BB * NCH];           // partial max
__device__ float g_pl[BB * NCH];           // partial sumexp
__device__ float g_pkbar[BB * NCH * II];   // partial weighted key sums
__device__ float g_kbar[BB * II];          // combined softmax-weighted key mean

// -------- cp.async helpers --------
__device__ __forceinline__ void cp_async16(void* dst_smem, const void* src_gmem) {
    unsigned d = (unsigned)__cvta_generic_to_shared(dst_smem);
    asm volatile("cp.async.cg.shared.global [%0], [%1], 16;\n" :: "r"(d), "l"(src_gmem));
}
__device__ __forceinline__ void cp_async_commit() {
    asm volatile("cp.async.commit_group;\n");
}
__device__ __forceinline__ void cp_async_wait1() {
    asm volatile("cp.async.wait_group 1;\n");
}
__device__ __forceinline__ void cp_async_wait0() {
    asm volatile("cp.async.wait_group 0;\n");
}

// ============================================================
// Kernel A1: partial projected-weight vectors (unchanged).
// ============================================================
__global__ void __launch_bounds__(256) prep_partial(
    const float* __restrict__ Wk, const float* __restrict__ Wq,
    const float* __restrict__ Wout)
{
    const int blk = blockIdx.x;
    const int mat = blk >> 7;
    const int rem = blk & 127;
    const int hs  = rem >> 4;
    const int ig  = rem & 15;
    const int i0  = ig * 32;
    const int h0  = hs * 64;
    const int tid = threadIdx.x;
    const int il   = tid & 31;
    const int hsub = tid >> 5;

    const float* W = mat ? Wq : Wk;

    __shared__ float wout_sh[64];
    __shared__ float red[256];
    if (tid < 64) wout_sh[tid] = Wout[h0 + tid];
    __syncthreads();

    float acc = 0.f;
    #pragma unroll
    for (int k = 0; k < 8; k++) {
        int hl = hsub * 8 + k;
        acc += W[(size_t)(h0 + hl) * II + i0 + il] * wout_sh[hl];
    }
    red[tid] = acc;
    __syncthreads();
    if (tid < 128) red[tid] += red[tid + 128];
    __syncthreads();
    if (tid < 64) red[tid] += red[tid + 64];
    __syncthreads();
    if (tid < 32) {
        float v = red[tid] + red[tid + 32];
        g_part[(mat * HSPLIT + hs) * II + i0 + tid] = v;
    }
}

// ============================================================
// Kernel A2: combine partials (unchanged).
// ============================================================
__global__ void __launch_bounds__(512) prep_combine(
    const float* __restrict__ query,
    const float* __restrict__ bq, const float* __restrict__ bk,
    const float* __restrict__ Wout)
{
    const int tid = threadIdx.x;
    if (blockIdx.x == 32) {
        float s = 0.f;
        #pragma unroll
        for (int hs = 0; hs < HSPLIT; hs++)
            s += g_part[hs * II + tid];
        g_w2[tid] = s;
        return;
    }
    const int b = blockIdx.x;
    __shared__ float wq2_sh[II];
    __shared__ float red[512];

    float s = 0.f;
    #pragma unroll
    for (int hs = 0; hs < HSPLIT; hs++)
        s += g_part[(HSPLIT + hs) * II + tid];
    wq2_sh[tid] = s;

    red[tid] = Wout[tid] * (bq[tid] + bk[tid]);
    __syncthreads();
    for (int off = 256; off > 0; off >>= 1) {
        if (tid < off) red[tid] += red[tid + off];
        __syncthreads();
    }
    float cbias = red[0];
    __syncthreads();

    red[tid] = query[(size_t)b * II + tid] * wq2_sh[tid];
    __syncthreads();
    for (int off = 256; off > 0; off >>= 1) {
        if (tid < off) red[tid] += red[tid + off];
        __syncthreads();
    }
    if (tid == 0) g_qoff[b] = red[0] + cbias;
}

// ============================================================
// Kernel B: streaming pass. TILE=8 -> ~33KB smem -> ~6 blocks/SM
// (near single wave). Mask preloaded to smem (off critical path).
// ============================================================
__global__ void __launch_bounds__(NTHREADS) main_pass(
    const float* __restrict__ key,
    const int* __restrict__ mask,
    float* __restrict__ out)
{
    const int b = blockIdx.x / NCH;
    const int c = blockIdx.x % NCH;
    const int tid = threadIdx.x;
    const int lane = tid & 31;
    const int warp = tid >> 5;
    const int s0 = c * CHUNK;
    const float* keyb = key + (size_t)b * SS * II + (size_t)s0 * II;

    extern __shared__ float smem[];
    float* buf0  = smem;                     // TILE*II floats (4096)
    float* buf1  = smem + TILE * II;         // TILE*II floats
    float* sc_sh = smem + 2 * TILE * II;     // TILE scores
    float* p_sh  = sc_sh + TILE;             // TILE probs
    int*   mask_sh = (int*)(p_sh + TILE);    // CHUNK ints

    // preload mask chunk (one coalesced load, off the per-tile path)
    if (tid < CHUNK) mask_sh[tid] = mask[(size_t)b * SS + s0 + tid];

    float w2r[16];
    #pragma unroll
    for (int k = 0; k < 16; k++) w2r[k] = g_w2[lane + 32 * k];

    const float qoff = g_qoff[b];

    float kbar0 = 0.f, kbar1 = 0.f;
    float l = 0.f;
    float m_run = -3.0e38f;

    // issue tile 0: TILE*II/4 = 1024 float4, 4 per thread
    {
        #pragma unroll
        for (int j = 0; j < 4; j++) {
            int idx = tid + j * NTHREADS;
            cp_async16(buf0 + idx * 4, keyb + idx * 4);
        }
        cp_async_commit();
    }

    for (int t = 0; t < NTILES; t++) {
        float* cur = (t & 1) ? buf1 : buf0;
        if (t + 1 < NTILES) {
            float* nxt = (t & 1) ? buf0 : buf1;
            const float* src = keyb + (size_t)(t + 1) * TILE * II;
            #pragma unroll
            for (int j = 0; j < 4; j++) {
                int idx = tid + j * NTHREADS;
                cp_async16(nxt + idx * 4, src + idx * 4);
            }
            cp_async_commit();
            cp_async_wait1();
        } else {
            cp_async_wait0();
        }
        __syncthreads();

        // ---- scores: warp w handles position w (TILE==8) ----
        {
            const int tt = warp;
            const float* kr = cur + tt * II;
            float acc = 0.f;
            #pragma unroll
            for (int k = 0; k < 16; k++)
                acc += kr[lane + 32 * k] * w2r[k];
            #pragma unroll
            for (int off = 16; off > 0; off >>= 1)
                acc += __shfl_down_sync(0xffffffffu, acc, off);
            if (lane == 0) {
                float sc = acc + qoff;
                if (mask_sh[t * TILE + tt] != 0) sc = NEG_INF_F;
                sc_sh[tt] = sc;
            }
        }
        __syncthreads();

        // coalesced attn_weight store (32B)
        if (tid < TILE)
            out[(size_t)BB * HH + (size_t)b * SS + s0 + t * TILE + tid] = sc_sh[tid];

        // ---- online softmax update (round-4 style) ----
        float mt = -3.0e38f;
        #pragma unroll
        for (int tt = 0; tt < TILE; tt++) mt = fmaxf(mt, sc_sh[tt]);
        float m_new = fmaxf(m_run, mt);
        float scale = __expf(m_run - m_new);

        if (tid < TILE) p_sh[tid] = __expf(sc_sh[tid] - m_new);
        __syncthreads();

        kbar0 *= scale;
        kbar1 *= scale;
        float tsum = 0.f;
        #pragma unroll
        for (int tt = 0; tt < TILE; tt++) {
            float p = p_sh[tt];
            tsum += p;
            kbar0 += p * cur[tt * II + tid];
            kbar1 += p * cur[tt * II + tid + 256];
        }
        l = l * scale + tsum;
        m_run = m_new;
        __syncthreads(); // buffer reuse fence
    }

    const int pidx = blockIdx.x;
    g_pkbar[(size_t)pidx * II + tid] = kbar0;
    g_pkbar[(size_t)pidx * II + tid + 256] = kbar1;
    if (tid == 0) { g_pm[pidx] = m_run; g_pl[pidx] = l; }
}

// ============================================================
// Kernel C1: combine chunk partials -> g_kbar[b][i].
// grid = 32, 256 threads, fat unrolled dual-accumulator loop.
// ============================================================
__global__ void __launch_bounds__(256) combine_kbar(void)
{
    const int b   = blockIdx.x;
    const int tid = threadIdx.x;
    const int lane = tid & 31;
    const int warp = tid >> 5;

    __shared__ float w_sh[NCH];
    __shared__ float invl_sh;

    if (warp == 0) {
        float pm = g_pm[b * NCH + lane];
        float pl = g_pl[b * NCH + lane];
        float M = pm;
        #pragma unroll
        for (int off = 16; off > 0; off >>= 1)
            M = fmaxf(M, __shfl_xor_sync(0xffffffffu, M, off));
        float w = __expf(pm - M);
        w_sh[lane] = w;
        float lw = pl * w;
        #pragma unroll
        for (int off = 16; off > 0; off >>= 1)
            lw += __shfl_xor_sync(0xffffffffu, lw, off);
        if (lane == 0) invl_sh = 1.f / lw;
    }
    __syncthreads();

    float kb0 = 0.f, kb1 = 0.f;
    #pragma unroll
    for (int c = 0; c < NCH; c++) {
        float w = w_sh[c];
        kb0 += g_pkbar[(size_t)(b * NCH + c) * II + tid] * w;
        kb1 += g_pkbar[(size_t)(b * NCH + c) * II + tid + 256] * w;
    }
    float invl = invl_sh;
    g_kbar[b * II + tid] = kb0 * invl;
    g_kbar[b * II + tid + 256] = kb1 * invl;
}

// ============================================================
// Kernel C2: projection. Each Wk row read ONCE chip-wide.
// grid = HH/8 = 64 blocks; 8 warps; warp w owns h = blk*8+w.
// All 32 kbar vectors staged in 64KB smem.
// ============================================================
__global__ void __launch_bounds__(256) project(
    const float* __restrict__ Wk, const float* __restrict__ bk,
    float* __restrict__ out)
{
    const int tid = threadIdx.x;
    const int lane = tid & 31;
    const int warp = tid >> 5;
    const int h = blockIdx.x * 8 + warp;

    extern __shared__ float kb_sh[];   // BB*II = 16384 floats = 64KB
    // stage g_kbar: 4096 float4 / 256 threads = 16 each
    float4* kb4s = (float4*)kb_sh;
    const float4* gk4 = (const float4*)g_kbar;
    #pragma unroll
    for (int j = 0; j < 16; j++)
        kb4s[tid + j * 256] = gk4[tid + j * 256];
    __syncthreads();

    // Wk row into registers: 512 floats = 4 float4 per lane
    const float4* w4 = (const float4*)(Wk + (size_t)h * II);
    float4 wr[4];
    #pragma unroll
    for (int j = 0; j < 4; j++) wr[j] = w4[lane + j * 32];
    const float bkh = bk[h];

    #pragma unroll 4
    for (int b = 0; b < BB; b++) {
        const float4* kb4 = (const float4*)(kb_sh + b * II);
        float acc = 0.f;
        #pragma unroll
        for (int j = 0; j < 4; j++) {
            float4 c4 = kb4[lane + j * 32];
            acc += wr[j].x * c4.x + wr[j].y * c4.y + wr[j].z * c4.z + wr[j].w * c4.w;
        }
        #pragma unroll
        for (int off = 16; off > 0; off >>= 1)
            acc += __shfl_down_sync(0xffffffffu, acc, off);
        if (lane == 0) out[b * HH + h] = acc + bkh;
    }
}

// ============================================================
extern "C" void kernel_launch(void* const* d_in, const int* in_sizes, int n_in,
                              void* d_out, int out_size) {
    const float* query = (const float*)d_in[0];
    const float* key   = (const float*)d_in[1];
    const int*   mask  = (const int*)d_in[2];
    const float* Wq   = (const float*)d_in[3];
    const float* bq   = (const float*)d_in[4];
    const float* Wk   = (const float*)d_in[5];
    const float* bk   = (const float*)d_in[6];
    const float* Wout = (const float*)d_in[7];
    float* out = (float*)d_out;

    const size_t smem_main = (2 * TILE * II + 2 * TILE) * sizeof(float) + CHUNK * sizeof(int);
    const size_t smem_proj = BB * II * sizeof(float);
    cudaFuncSetAttribute(main_pass, cudaFuncAttributeMaxDynamicSharedMemorySize, (int)smem_main);
    cudaFuncSetAttribute(project, cudaFuncAttributeMaxDynamicSharedMemorySize, (int)smem_proj);

    prep_partial<<<256, 256>>>(Wk, Wq, Wout);
    prep_combine<<<33, 512>>>(query, bq, bk, Wout);
    main_pass<<<BB * NCH, NTHREADS, smem_main>>>(key, mask, out);
    combine_kbar<<<BB, 256>>>();
    project<<<HH / 8, 256, smem_proj>>>(Wk, bk, out);
}

// round 7
// speedup vs baseline: 1.4748x; 1.0950x over previous
#include <cuda_runtime.h>
#include <math.h>
#include <stdint.h>

#define BB 32
#define SS 4096
#define II 512
#define HH 512
#define NCH 16
#define CHUNK (SS / NCH)      // 256 positions per block
#define TILE 8                // positions per shared tile
#define NTILES (CHUNK / TILE) // 32
#define NBUF 3
#define NTHREADS 256
#define NEG_INF_F (-1e18f)
#define HSPLIT 8

// -------- persistent device scratch (no allocations allowed) --------
__device__ float g_part[2 * HSPLIT * II];  // [mat][hs][i] partials
__device__ float g_w2[II];                 // Wk^T @ Wout
__device__ float g_qoff[BB];               // per-batch additive score offset
__device__ float g_pm[BB * NCH];           // partial max
__device__ float g_pl[BB * NCH];           // partial sumexp
__device__ float g_pkbar[BB * NCH * II];   // partial weighted key sums
__device__ float g_kbar[BB * II];          // combined softmax-weighted key mean

// -------- cp.async helpers --------
__device__ __forceinline__ void cp_async16(void* dst_smem, const void* src_gmem) {
    unsigned d = (unsigned)__cvta_generic_to_shared(dst_smem);
    asm volatile("cp.async.cg.shared.global [%0], [%1], 16;\n" :: "r"(d), "l"(src_gmem));
}
__device__ __forceinline__ void cp_async_commit() {
    asm volatile("cp.async.commit_group;\n");
}
__device__ __forceinline__ void cp_async_wait1() {
    asm volatile("cp.async.wait_group 1;\n");
}
__device__ __forceinline__ void cp_async_wait0() {
    asm volatile("cp.async.wait_group 0;\n");
}

// ============================================================
// Kernel A1: partial projected-weight vectors (unchanged).
// ============================================================
__global__ void __launch_bounds__(256) prep_partial(
    const float* __restrict__ Wk, const float* __restrict__ Wq,
    const float* __restrict__ Wout)
{
    const int blk = blockIdx.x;
    const int mat = blk >> 7;
    const int rem = blk & 127;
    const int hs  = rem >> 4;
    const int ig  = rem & 15;
    const int i0  = ig * 32;
    const int h0  = hs * 64;
    const int tid = threadIdx.x;
    const int il   = tid & 31;
    const int hsub = tid >> 5;

    const float* W = mat ? Wq : Wk;

    __shared__ float wout_sh[64];
    __shared__ float red[256];
    if (tid < 64) wout_sh[tid] = Wout[h0 + tid];
    __syncthreads();

    float acc = 0.f;
    #pragma unroll
    for (int k = 0; k < 8; k++) {
        int hl = hsub * 8 + k;
        acc += W[(size_t)(h0 + hl) * II + i0 + il] * wout_sh[hl];
    }
    red[tid] = acc;
    __syncthreads();
    if (tid < 128) red[tid] += red[tid + 128];
    __syncthreads();
    if (tid < 64) red[tid] += red[tid + 64];
    __syncthreads();
    if (tid < 32) {
        float v = red[tid] + red[tid + 32];
        g_part[(mat * HSPLIT + hs) * II + i0 + tid] = v;
    }
}

// ============================================================
// Kernel A2: combine partials (unchanged).
// ============================================================
__global__ void __launch_bounds__(512) prep_combine(
    const float* __restrict__ query,
    const float* __restrict__ bq, const float* __restrict__ bk,
    const float* __restrict__ Wout)
{
    const int tid = threadIdx.x;
    if (blockIdx.x == 32) {
        float s = 0.f;
        #pragma unroll
        for (int hs = 0; hs < HSPLIT; hs++)
            s += g_part[hs * II + tid];
        g_w2[tid] = s;
        return;
    }
    const int b = blockIdx.x;
    __shared__ float wq2_sh[II];
    __shared__ float red[512];

    float s = 0.f;
    #pragma unroll
    for (int hs = 0; hs < HSPLIT; hs++)
        s += g_part[(HSPLIT + hs) * II + tid];
    wq2_sh[tid] = s;

    red[tid] = Wout[tid] * (bq[tid] + bk[tid]);
    __syncthreads();
    for (int off = 256; off > 0; off >>= 1) {
        if (tid < off) red[tid] += red[tid + off];
        __syncthreads();
    }
    float cbias = red[0];
    __syncthreads();

    red[tid] = query[(size_t)b * II + tid] * wq2_sh[tid];
    __syncthreads();
    for (int off = 256; off > 0; off >>= 1) {
        if (tid < off) red[tid] += red[tid + off];
        __syncthreads();
    }
    if (tid == 0) g_qoff[b] = red[0] + cbias;
}

// ============================================================
// Kernel B: streaming pass. 512 blocks (single wave @4/SM),
// triple-buffered cp.async, 2 barriers per tile (issue-at-end
// removes the buffer-reuse barrier).
// ============================================================
__global__ void __launch_bounds__(NTHREADS) main_pass(
    const float* __restrict__ key,
    const int* __restrict__ mask,
    float* __restrict__ out)
{
    const int b = blockIdx.x / NCH;
    const int c = blockIdx.x % NCH;
    const int tid = threadIdx.x;
    const int lane = tid & 31;
    const int warp = tid >> 5;
    const int s0 = c * CHUNK;
    const float* keyb = key + (size_t)b * SS * II + (size_t)s0 * II;

    extern __shared__ float smem[];
    float* bufs = smem;                          // NBUF * TILE*II floats
    float* sc_sh = smem + NBUF * TILE * II;      // TILE scores
    float* p_sh  = sc_sh + TILE;                 // TILE probs
    int*   mask_sh = (int*)(p_sh + TILE);        // CHUNK ints

    // preload mask chunk (coalesced, off the per-tile path)
    mask_sh[tid] = mask[(size_t)b * SS + s0 + tid];

    float w2r[16];
    #pragma unroll
    for (int k = 0; k < 16; k++) w2r[k] = g_w2[lane + 32 * k];

    const float qoff = g_qoff[b];

    float kbar0 = 0.f, kbar1 = 0.f;
    float l = 0.f;
    float m_run = -3.0e38f;

    // preload tiles 0 and 1 (each: 1024 float4, 4 per thread)
    #pragma unroll
    for (int pt = 0; pt < 2; pt++) {
        const float* src = keyb + (size_t)pt * TILE * II;
        float* dst = bufs + pt * TILE * II;
        #pragma unroll
        for (int j = 0; j < 4; j++) {
            int idx = tid + j * NTHREADS;
            cp_async16(dst + idx * 4, src + idx * 4);
        }
        cp_async_commit();
    }

    for (int t = 0; t < NTILES; t++) {
        float* cur = bufs + (t % NBUF) * TILE * II;
        // pending groups at this point: tile t (maybe done), tile t+1
        if (t + 1 < NTILES) cp_async_wait1();
        else cp_async_wait0();
        __syncthreads();

        // ---- scores: warp w handles position w (TILE==8) ----
        {
            const float* kr = cur + warp * II;
            float acc = 0.f;
            #pragma unroll
            for (int k = 0; k < 16; k++)
                acc += kr[lane + 32 * k] * w2r[k];
            #pragma unroll
            for (int off = 16; off > 0; off >>= 1)
                acc += __shfl_down_sync(0xffffffffu, acc, off);
            if (lane == 0) {
                float sc = acc + qoff;
                if (mask_sh[t * TILE + warp] != 0) sc = NEG_INF_F;
                sc_sh[warp] = sc;
            }
        }
        __syncthreads();

        // coalesced attn_weight store (32B)
        if (tid < TILE)
            out[(size_t)BB * HH + (size_t)b * SS + s0 + t * TILE + tid] = sc_sh[tid];

        // ---- online softmax update ----
        float mt = -3.0e38f;
        #pragma unroll
        for (int tt = 0; tt < TILE; tt++) mt = fmaxf(mt, sc_sh[tt]);
        float m_new = fmaxf(m_run, mt);
        float scale = __expf(m_run - m_new);

        float pr[TILE];
        #pragma unroll
        for (int tt = 0; tt < TILE; tt++) pr[tt] = __expf(sc_sh[tt] - m_new);

        kbar0 *= scale;
        kbar1 *= scale;
        float tsum = 0.f;
        #pragma unroll
        for (int tt = 0; tt < TILE; tt++) {
            float p = pr[tt];
            tsum += p;
            kbar0 += p * cur[tt * II + tid];
            kbar1 += p * cur[tt * II + tid + 256];
        }
        l = l * scale + tsum;
        m_run = m_new;

        // issue tile t+2 into buf[(t+2)%3] (last read at iter t-1;
        // two barriers have passed since -> safe, no extra barrier)
        if (t + 2 < NTILES) {
            const float* src = keyb + (size_t)(t + 2) * TILE * II;
            float* nxt = bufs + ((t + 2) % NBUF) * TILE * II;
            #pragma unroll
            for (int j = 0; j < 4; j++) {
                int idx = tid + j * NTHREADS;
                cp_async16(nxt + idx * 4, src + idx * 4);
            }
            cp_async_commit();
        }
    }

    const int pidx = blockIdx.x;
    g_pkbar[(size_t)pidx * II + tid] = kbar0;
    g_pkbar[(size_t)pidx * II + tid + 256] = kbar1;
    if (tid == 0) { g_pm[pidx] = m_run; g_pl[pidx] = l; }
}

// ============================================================
// Kernel C1: combine chunk partials -> g_kbar[b][i].
// grid = BB*4 (128 blocks), 128 threads; each block: 128 i-values.
// ============================================================
__global__ void __launch_bounds__(128) combine_kbar(void)
{
    const int b   = blockIdx.x >> 2;
    const int i0  = (blockIdx.x & 3) * 128;
    const int tid = threadIdx.x;
    const int lane = tid & 31;
    const int warp = tid >> 5;

    __shared__ float w_sh[NCH];
    __shared__ float invl_sh;

    if (warp == 0) {
        float pm = (lane < NCH) ? g_pm[b * NCH + lane] : -3.0e38f;
        float pl = (lane < NCH) ? g_pl[b * NCH + lane] : 0.f;
        float M = pm;
        #pragma unroll
        for (int off = 16; off > 0; off >>= 1)
            M = fmaxf(M, __shfl_xor_sync(0xffffffffu, M, off));
        float w = __expf(pm - M);
        if (lane < NCH) w_sh[lane] = w;
        float lw = pl * w;
        #pragma unroll
        for (int off = 16; off > 0; off >>= 1)
            lw += __shfl_xor_sync(0xffffffffu, lw, off);
        if (lane == 0) invl_sh = 1.f / lw;
    }
    __syncthreads();

    const int i = i0 + tid;
    float kb = 0.f;
    #pragma unroll
    for (int c = 0; c < NCH; c++)
        kb += g_pkbar[(size_t)(b * NCH + c) * II + i] * w_sh[c];
    g_kbar[b * II + i] = kb * invl_sh;
}

// ============================================================
// Kernel C2: projection. Each Wk row read ONCE chip-wide.
// grid = HH/8 = 64 blocks; warp w owns h = blk*8+w.
// ============================================================
__global__ void __launch_bounds__(256) project(
    const float* __restrict__ Wk, const float* __restrict__ bk,
    float* __restrict__ out)
{
    const int tid = threadIdx.x;
    const int lane = tid & 31;
    const int warp = tid >> 5;
    const int h = blockIdx.x * 8 + warp;

    extern __shared__ float kb_sh[];   // BB*II floats = 64KB
    float4* kb4s = (float4*)kb_sh;
    const float4* gk4 = (const float4*)g_kbar;
    #pragma unroll
    for (int j = 0; j < 16; j++)
        kb4s[tid + j * 256] = gk4[tid + j * 256];
    __syncthreads();

    const float4* w4 = (const float4*)(Wk + (size_t)h * II);
    float4 wr[4];
    #pragma unroll
    for (int j = 0; j < 4; j++) wr[j] = w4[lane + j * 32];
    const float bkh = bk[h];

    #pragma unroll 4
    for (int b = 0; b < BB; b++) {
        const float4* kb4 = (const float4*)(kb_sh + b * II);
        float acc = 0.f;
        #pragma unroll
        for (int j = 0; j < 4; j++) {
            float4 c4 = kb4[lane + j * 32];
            acc += wr[j].x * c4.x + wr[j].y * c4.y + wr[j].z * c4.z + wr[j].w * c4.w;
        }
        #pragma unroll
        for (int off = 16; off > 0; off >>= 1)
            acc += __shfl_down_sync(0xffffffffu, acc, off);
        if (lane == 0) out[b * HH + h] = acc + bkh;
    }
}

// ============================================================
extern "C" void kernel_launch(void* const* d_in, const int* in_sizes, int n_in,
                              void* d_out, int out_size) {
    const float* query = (const float*)d_in[0];
    const float* key   = (const float*)d_in[1];
    const int*   mask  = (const int*)d_in[2];
    const float* Wq   = (const float*)d_in[3];
    const float* bq   = (const float*)d_in[4];
    const float* Wk   = (const float*)d_in[5];
    const float* bk   = (const float*)d_in[6];
    const float* Wout = (const float*)d_in[7];
    float* out = (float*)d_out;

    const size_t smem_main = (NBUF * TILE * II + 2 * TILE) * sizeof(float) + CHUNK * sizeof(int);
    const size_t smem_proj = BB * II * sizeof(float);
    cudaFuncSetAttribute(main_pass, cudaFuncAttributeMaxDynamicSharedMemorySize, (int)smem_main);
    cudaFuncSetAttribute(project, cudaFuncAttributeMaxDynamicSharedMemorySize, (int)smem_proj);

    prep_partial<<<256, 256>>>(Wk, Wq, Wout);
    prep_combine<<<33, 512>>>(query, bq, bk, Wout);
    main_pass<<<BB * NCH, NTHREADS, smem_main>>>(key, mask, out);
    combine_kbar<<<BB * 4, 128>>>();
    project<<<HH / 8, 256, smem_proj>>>(Wk, bk, out);
}